// round 14
// baseline (speedup 1.0000x reference)
#include <cuda_runtime.h>
#include <cuda_fp16.h>
#include <math.h>
#include <stdint.h>

#define B_  8
#define T_  4096
#define C_  512
#define U_  512
#define NG  1536            // 3*U
#define K_  1024            // 2*C
#define S_  128             // scan chunks
#define CH_ 32              // chunk length (S_*CH_ == T_)
#define TP_ 4097            // padded rows per batch (zero row at t=T)

#define BM  128
#define BN  128
#define BK  64
#define NKK (K_ / BK)       // 16 k-slices
#define NSTAGE 3
#define STAGE_BYTES 32768   // A 16K | W 16K
#define SMEM_TOTAL (NSTAGE * STAGE_BYTES)

#define NWBLK ((NG / 32) * (K_ / 32))        // 1536 prep_w blocks
#define NA8   ((B_ * TP_ * C_) / 8)          // prep_a items (8 elems each)
#define NABLK ((NA8 + 255) / 256)

// ---- device scratch (allocation-free rule) --------------------------------
__device__ __align__(128) __half g_a16[B_ * TP_ * C_];
__device__ __align__(128) __half g_w16[NG * K_];    // [n][k]
__device__ __align__(128) __half g_gates16[(size_t)B_ * T_ * NG]; // fp16 gates
__device__ __align__(128) float g_cend[B_ * S_ * U_];
__device__ __align__(128) float g_fprod[B_ * S_ * U_];

// ---------------------------------------------------------------------------
__device__ __forceinline__ uint32_t smem_u32(const void* p) {
    uint32_t a;
    asm("{ .reg .u64 t; cvta.to.shared.u64 t, %1; cvt.u32.u64 %0, t; }" : "=r"(a) : "l"(p));
    return a;
}
__device__ __forceinline__ void cp16(uint32_t saddr, const void* gaddr) {
    asm volatile("cp.async.cg.shared.global [%0], [%1], 16;" :: "r"(saddr), "l"(gaddr));
}
__device__ __forceinline__ void cp_commit() {
    asm volatile("cp.async.commit_group;" ::: "memory");
}
__device__ __forceinline__ void cp_wait1() {
    asm volatile("cp.async.wait_group 1;" ::: "memory");
}
__device__ __forceinline__ void ldm_x4(uint32_t* r, uint32_t addr) {
    asm volatile("ldmatrix.sync.aligned.m8n8.x4.shared.b16 {%0,%1,%2,%3}, [%4];"
                 : "=r"(r[0]), "=r"(r[1]), "=r"(r[2]), "=r"(r[3]) : "r"(addr));
}
__device__ __forceinline__ void mma_f16(float* d, const uint32_t* a, uint32_t b0, uint32_t b1) {
    asm volatile(
        "mma.sync.aligned.m16n8k16.row.col.f32.f16.f16.f32 "
        "{%0,%1,%2,%3}, {%4,%5,%6,%7}, {%8,%9}, {%0,%1,%2,%3};"
        : "+f"(d[0]), "+f"(d[1]), "+f"(d[2]), "+f"(d[3])
        : "r"(a[0]), "r"(a[1]), "r"(a[2]), "r"(a[3]), "r"(b0), "r"(b1));
}
// unpack uint2 (4 halfs) to 4 floats
__device__ __forceinline__ void h4_to_f4(uint2 v, float* f) {
    __half2 h0 = *(__half2*)&v.x;
    __half2 h1 = *(__half2*)&v.y;
    float2 a = __half22float2(h0), b = __half22float2(h1);
    f[0] = a.x; f[1] = a.y; f[2] = b.x; f[3] = b.y;
}

// ---------------------------------------------------------------------------
// Fused prep: blocks [0, NWBLK) transpose W to fp16 [n][k];
//             blocks [NWBLK, ...) convert A to fp16 (8 elems/thread, 16B store)
// ---------------------------------------------------------------------------
__global__ void __launch_bounds__(256) prep_fused(const float* __restrict__ in,
                                                  const float* __restrict__ W) {
    if (blockIdx.x < NWBLK) {
        __shared__ float tile[32][33];
        const int wb = blockIdx.x;
        const int n0 = (wb % (NG / 32)) * 32;
        const int k0 = (wb / (NG / 32)) * 32;
        const int tx = threadIdx.x & 31;
        const int ty = threadIdx.x >> 5;
#pragma unroll
        for (int j = 0; j < 4; j++) {
            int k = ty + j * 8;
            tile[k][tx] = W[(size_t)(k0 + k) * NG + n0 + tx];
        }
        __syncthreads();
#pragma unroll
        for (int j = 0; j < 4; j++) {
            int n = ty + j * 8;
            g_w16[(size_t)(n0 + n) * K_ + k0 + tx] = __float2half_rn(tile[tx][n]);
        }
    } else {
        int idx = (blockIdx.x - NWBLK) * blockDim.x + threadIdx.x;
        if (idx >= NA8) return;
        int c8 = idx & (C_ / 8 - 1);
        int r  = idx >> 6;
        int b  = r / TP_;
        int t  = r - b * TP_;
        uint4 pack;
        if (t < T_) {
            const float* src = in + ((size_t)(b * T_ + t)) * C_ + c8 * 8;
            float4 v0 = *(const float4*)(src);
            float4 v1 = *(const float4*)(src + 4);
            __half2 h0 = __floats2half2_rn(v0.x, v0.y);
            __half2 h1 = __floats2half2_rn(v0.z, v0.w);
            __half2 h2 = __floats2half2_rn(v1.x, v1.y);
            __half2 h3 = __floats2half2_rn(v1.z, v1.w);
            pack.x = *(uint32_t*)&h0; pack.y = *(uint32_t*)&h1;
            pack.z = *(uint32_t*)&h2; pack.w = *(uint32_t*)&h3;
        } else {
            pack = make_uint4(0, 0, 0, 0);
        }
        *(uint4*)(g_a16 + (size_t)idx * 8) = pack;
    }
}

// ---------------------------------------------------------------------------
// HMMA GEMM, single-product fp16, BK=64, 2 CTAs/SM. (unchanged — at ceiling)
// ---------------------------------------------------------------------------
__global__ void __launch_bounds__(256, 2) gemm_mma(const float* __restrict__ bias) {
    extern __shared__ char smem[];
    const uint32_t sb = smem_u32(smem);
    const int tid  = threadIdx.x;
    const int wid  = tid >> 5;
    const int lane = tid & 31;

    const int bn  = blockIdx.x, bm = blockIdx.y;
    const int gm0 = bm * BM;
    const int b   = gm0 >> 12;
    const int t0  = gm0 & (T_ - 1);
    const int row0 = b * TP_ + t0;
    const int n0  = bn * BN;

    int ldr[4], ldc[4];
    uint32_t ldo[4];
    const __half* pa[4];
    const __half* pw[4];
#pragma unroll
    for (int j = 0; j < 4; j++) {
        int tt = tid + j * 256;
        ldr[j] = tt >> 3;
        ldc[j] = tt & 7;
        ldo[j] = ldr[j] * 128 + ((ldc[j] ^ (ldr[j] & 7)) << 4);
        pa[j] = g_a16 + (size_t)(row0 + ldr[j]) * C_ + ldc[j] * 8;
        pw[j] = g_w16 + (size_t)(n0 + ldr[j]) * K_ + ldc[j] * 8;
    }

    auto issue = [&](int kk) {
        const uint32_t st = sb + (kk % NSTAGE) * STAGE_BYTES;
        const int kb = kk * BK;
#pragma unroll
        for (int j = 0; j < 4; j++) {
            cp16(st + ldo[j],          pa[j] + kb);
            cp16(st + 16384 + ldo[j],  pw[j] + kb);
        }
    };

    const int wm0 = (wid >> 2) * 64;
    const int wn0 = (wid & 3) * 32;

    float acc[4][4][4];
#pragma unroll
    for (int i = 0; i < 4; i++)
#pragma unroll
        for (int j = 0; j < 4; j++)
#pragma unroll
            for (int q = 0; q < 4; q++) acc[i][j][q] = 0.0f;

    issue(0); cp_commit();
    issue(1); cp_commit();

    for (int kk = 0; kk < NKK; kk++) {
        cp_wait1();
        __syncthreads();
        if (kk + 2 < NKK) issue(kk + 2);
        cp_commit();

        const uint32_t st = sb + (kk % NSTAGE) * STAGE_BYTES;
        const uint32_t As = st, Ws = st + 16384;

#pragma unroll
        for (int ks = 0; ks < 4; ks++) {
            const int ch = ks * 2 + (lane >> 4);
            uint32_t a[4][4], w[2][4];
#pragma unroll
            for (int mt = 0; mt < 4; mt++) {
                int row = wm0 + mt * 16 + (lane & 15);
                uint32_t off = row * 128 + ((ch ^ (row & 7)) << 4);
                ldm_x4(a[mt], As + off);
            }
#pragma unroll
            for (int bt = 0; bt < 2; bt++) {
                int row = wn0 + bt * 16 + (lane & 15);
                uint32_t off = row * 128 + ((ch ^ (row & 7)) << 4);
                ldm_x4(w[bt], Ws + off);
            }
#pragma unroll
            for (int mt = 0; mt < 4; mt++)
#pragma unroll
                for (int nt = 0; nt < 4; nt++)
                    mma_f16(acc[mt][nt], a[mt], w[nt >> 1][nt & 1], w[nt >> 1][2 + (nt & 1)]);
        }
    }

    const bool is_tanh = (n0 < U_);
    const int grow = lane >> 2;
    const int gcol = (lane & 3) * 2;
#pragma unroll
    for (int mt = 0; mt < 4; mt++) {
#pragma unroll
        for (int nt = 0; nt < 4; nt++) {
            int n = n0 + wn0 + nt * 8 + gcol;
            float b0 = __ldg(bias + n);
            float b1 = __ldg(bias + n + 1);
#pragma unroll
            for (int h = 0; h < 2; h++) {
                int m = gm0 + wm0 + mt * 16 + grow + h * 8;
                float v0 = acc[mt][nt][2 * h]     + b0;
                float v1 = acc[mt][nt][2 * h + 1] + b1;
                if (is_tanh) {
                    float e0 = __expf(2.0f * v0), e1 = __expf(2.0f * v1);
                    v0 = 1.0f - 2.0f / (e0 + 1.0f);
                    v1 = 1.0f - 2.0f / (e1 + 1.0f);
                } else {
                    v0 = 1.0f / (1.0f + __expf(-v0));
                    v1 = 1.0f / (1.0f + __expf(-v1));
                }
                *(__half2*)(g_gates16 + (size_t)m * NG + n) = __floats2half2_rn(v0, v1);
            }
        }
    }
}

// ---------------------------------------------------------------------------
// Scan passes: 4 channels/thread, 8B gate loads, 128 threads/block.
// grid (1, S_, B_) = 1024 blocks.
// ---------------------------------------------------------------------------
__global__ void __launch_bounds__(128) scan_partial() {
    int u = threadIdx.x * 4;
    int s = blockIdx.y;
    int b = blockIdx.z;
    const __half* gp = g_gates16 + ((size_t)(b * T_ + s * CH_)) * NG;
    float c[4] = {0.f, 0.f, 0.f, 0.f};
    float F[4] = {1.f, 1.f, 1.f, 1.f};
    for (int t = 0; t < CH_; t++) {
        float x[4], f[4];
        h4_to_f4(*(const uint2*)(gp + (size_t)t * NG + u), x);
        h4_to_f4(*(const uint2*)(gp + (size_t)t * NG + U_ + u), f);
#pragma unroll
        for (int q = 0; q < 4; q++) {
            c[q] = fmaf(f[q], c[q] - x[q], x[q]);
            F[q] *= f[q];
        }
    }
    int off = (b * S_ + s) * U_ + u;
    *(float4*)(g_cend  + off) = make_float4(c[0], c[1], c[2], c[3]);
    *(float4*)(g_fprod + off) = make_float4(F[0], F[1], F[2], F[3]);
}

__global__ void __launch_bounds__(128) scan_final(float* __restrict__ out) {
    int u = threadIdx.x * 4;
    int s = blockIdx.y;
    int b = blockIdx.z;

    // carry prefix over chunk summaries (L2-resident), unroll for MLP
    float c[4] = {0.f, 0.f, 0.f, 0.f};
#pragma unroll 4
    for (int sp = 0; sp < s; sp++) {
        int off = (b * S_ + sp) * U_ + u;
        float4 F = *(const float4*)(g_fprod + off);
        float4 E = *(const float4*)(g_cend  + off);
        c[0] = fmaf(F.x, c[0], E.x);
        c[1] = fmaf(F.y, c[1], E.y);
        c[2] = fmaf(F.z, c[2], E.z);
        c[3] = fmaf(F.w, c[3], E.w);
    }

    const __half* gp = g_gates16 + ((size_t)(b * T_ + s * CH_)) * NG;
    float* op = out + ((size_t)(b * T_ + s * CH_)) * U_;
#pragma unroll 4
    for (int t = 0; t < CH_; t++) {
        float x[4], f[4], o[4];
        h4_to_f4(*(const uint2*)(gp + (size_t)t * NG + u), x);
        h4_to_f4(*(const uint2*)(gp + (size_t)t * NG + U_ + u), f);
        h4_to_f4(*(const uint2*)(gp + (size_t)t * NG + 2 * U_ + u), o);
        float4 r;
        c[0] = fmaf(f[0], c[0] - x[0], x[0]);  r.x = o[0] * c[0];
        c[1] = fmaf(f[1], c[1] - x[1], x[1]);  r.y = o[1] * c[1];
        c[2] = fmaf(f[2], c[2] - x[2], x[2]);  r.z = o[2] * c[2];
        c[3] = fmaf(f[3], c[3] - x[3], x[3]);  r.w = o[3] * c[3];
        *(float4*)(op + (size_t)t * U_ + u) = r;
    }
}

// ---------------------------------------------------------------------------
extern "C" void kernel_launch(void* const* d_in, const int* in_sizes, int n_in,
                              void* d_out, int out_size) {
    const float* in   = (const float*)d_in[0];
    const float* W    = (const float*)d_in[1];
    const float* bias = (const float*)d_in[2];
    float* out = (float*)d_out;

    prep_fused<<<NWBLK + NABLK, 256>>>(in, W);

    cudaFuncSetAttribute(gemm_mma, cudaFuncAttributeMaxDynamicSharedMemorySize, SMEM_TOTAL);
    dim3 gGemm(NG / BN, (B_ * T_) / BM);   // (12, 256)
    gemm_mma<<<gGemm, 256, SMEM_TOTAL>>>(bias);

    dim3 gScan(1, S_, B_);                 // 1024 blocks
    scan_partial<<<gScan, 128>>>();
    scan_final<<<gScan, 128>>>(out);
}

// round 15
// speedup vs baseline: 1.0457x; 1.0457x over previous
#include <cuda_runtime.h>
#include <cuda_fp16.h>
#include <math.h>
#include <stdint.h>

#define B_  8
#define T_  4096
#define C_  512
#define U_  512
#define NG  1536            // 3*U
#define K_  1024            // 2*C
#define S_  64              // scan chunks
#define CH_ 64              // chunk length (S_*CH_ == T_)
#define TP_ 4097            // padded rows per batch (zero row at t=T)

#define BM  128
#define BN  128
#define BK  64
#define NKK (K_ / BK)       // 16 k-slices
#define NSTAGE 3
#define STAGE_BYTES 32768   // A 16K | W 16K
#define SMEM_TOTAL (NSTAGE * STAGE_BYTES)

#define NWBLK ((NG / 32) * (K_ / 32))        // 1536 prep_w blocks
#define NA8   ((B_ * TP_ * C_) / 8)          // prep_a items (8 elems each)
#define NABLK ((NA8 + 255) / 256)

// ---- device scratch (allocation-free rule) --------------------------------
__device__ __align__(128) __half g_a16[B_ * TP_ * C_];
__device__ __align__(128) __half g_w16[NG * K_];    // [n][k]
__device__ __align__(128) __half g_gates16[(size_t)B_ * T_ * NG]; // fp16 gates
__device__ float g_cend[B_ * S_ * U_];
__device__ float g_fprod[B_ * S_ * U_];

// ---------------------------------------------------------------------------
__device__ __forceinline__ uint32_t smem_u32(const void* p) {
    uint32_t a;
    asm("{ .reg .u64 t; cvta.to.shared.u64 t, %1; cvt.u32.u64 %0, t; }" : "=r"(a) : "l"(p));
    return a;
}
__device__ __forceinline__ void cp16(uint32_t saddr, const void* gaddr) {
    asm volatile("cp.async.cg.shared.global [%0], [%1], 16;" :: "r"(saddr), "l"(gaddr));
}
__device__ __forceinline__ void cp_commit() {
    asm volatile("cp.async.commit_group;" ::: "memory");
}
__device__ __forceinline__ void cp_wait1() {
    asm volatile("cp.async.wait_group 1;" ::: "memory");
}
__device__ __forceinline__ void ldm_x4(uint32_t* r, uint32_t addr) {
    asm volatile("ldmatrix.sync.aligned.m8n8.x4.shared.b16 {%0,%1,%2,%3}, [%4];"
                 : "=r"(r[0]), "=r"(r[1]), "=r"(r[2]), "=r"(r[3]) : "r"(addr));
}
__device__ __forceinline__ void mma_f16(float* d, const uint32_t* a, uint32_t b0, uint32_t b1) {
    asm volatile(
        "mma.sync.aligned.m16n8k16.row.col.f32.f16.f16.f32 "
        "{%0,%1,%2,%3}, {%4,%5,%6,%7}, {%8,%9}, {%0,%1,%2,%3};"
        : "+f"(d[0]), "+f"(d[1]), "+f"(d[2]), "+f"(d[3])
        : "r"(a[0]), "r"(a[1]), "r"(a[2]), "r"(a[3]), "r"(b0), "r"(b1));
}

// ---------------------------------------------------------------------------
// Fused prep: blocks [0, NWBLK) transpose W to fp16 [n][k];
//             blocks [NWBLK, ...) convert A to fp16 (8 elems/thread, 16B store)
// ---------------------------------------------------------------------------
__global__ void __launch_bounds__(256) prep_fused(const float* __restrict__ in,
                                                  const float* __restrict__ W) {
    if (blockIdx.x < NWBLK) {
        __shared__ float tile[32][33];
        const int wb = blockIdx.x;
        const int n0 = (wb % (NG / 32)) * 32;
        const int k0 = (wb / (NG / 32)) * 32;
        const int tx = threadIdx.x & 31;
        const int ty = threadIdx.x >> 5;
#pragma unroll
        for (int j = 0; j < 4; j++) {
            int k = ty + j * 8;
            tile[k][tx] = W[(size_t)(k0 + k) * NG + n0 + tx];
        }
        __syncthreads();
#pragma unroll
        for (int j = 0; j < 4; j++) {
            int n = ty + j * 8;
            g_w16[(size_t)(n0 + n) * K_ + k0 + tx] = __float2half_rn(tile[tx][n]);
        }
    } else {
        int idx = (blockIdx.x - NWBLK) * blockDim.x + threadIdx.x;
        if (idx >= NA8) return;
        int c8 = idx & (C_ / 8 - 1);
        int r  = idx >> 6;
        int b  = r / TP_;
        int t  = r - b * TP_;
        uint4 pack;
        if (t < T_) {
            const float* src = in + ((size_t)(b * T_ + t)) * C_ + c8 * 8;
            float4 v0 = *(const float4*)(src);
            float4 v1 = *(const float4*)(src + 4);
            __half2 h0 = __floats2half2_rn(v0.x, v0.y);
            __half2 h1 = __floats2half2_rn(v0.z, v0.w);
            __half2 h2 = __floats2half2_rn(v1.x, v1.y);
            __half2 h3 = __floats2half2_rn(v1.z, v1.w);
            pack.x = *(uint32_t*)&h0; pack.y = *(uint32_t*)&h1;
            pack.z = *(uint32_t*)&h2; pack.w = *(uint32_t*)&h3;
        } else {
            pack = make_uint4(0, 0, 0, 0);
        }
        *(uint4*)(g_a16 + (size_t)idx * 8) = pack;
    }
}

// ---------------------------------------------------------------------------
// HMMA GEMM, single-product fp16, BK=64, 2 CTAs/SM. (at measured HMMA ceiling)
// ---------------------------------------------------------------------------
__global__ void __launch_bounds__(256, 2) gemm_mma(const float* __restrict__ bias) {
    extern __shared__ char smem[];
    const uint32_t sb = smem_u32(smem);
    const int tid  = threadIdx.x;
    const int wid  = tid >> 5;
    const int lane = tid & 31;

    const int bn  = blockIdx.x, bm = blockIdx.y;
    const int gm0 = bm * BM;
    const int b   = gm0 >> 12;
    const int t0  = gm0 & (T_ - 1);
    const int row0 = b * TP_ + t0;
    const int n0  = bn * BN;

    int ldr[4], ldc[4];
    uint32_t ldo[4];
    const __half* pa[4];
    const __half* pw[4];
#pragma unroll
    for (int j = 0; j < 4; j++) {
        int tt = tid + j * 256;
        ldr[j] = tt >> 3;
        ldc[j] = tt & 7;
        ldo[j] = ldr[j] * 128 + ((ldc[j] ^ (ldr[j] & 7)) << 4);
        pa[j] = g_a16 + (size_t)(row0 + ldr[j]) * C_ + ldc[j] * 8;
        pw[j] = g_w16 + (size_t)(n0 + ldr[j]) * K_ + ldc[j] * 8;
    }

    auto issue = [&](int kk) {
        const uint32_t st = sb + (kk % NSTAGE) * STAGE_BYTES;
        const int kb = kk * BK;
#pragma unroll
        for (int j = 0; j < 4; j++) {
            cp16(st + ldo[j],          pa[j] + kb);
            cp16(st + 16384 + ldo[j],  pw[j] + kb);
        }
    };

    const int wm0 = (wid >> 2) * 64;
    const int wn0 = (wid & 3) * 32;

    float acc[4][4][4];
#pragma unroll
    for (int i = 0; i < 4; i++)
#pragma unroll
        for (int j = 0; j < 4; j++)
#pragma unroll
            for (int q = 0; q < 4; q++) acc[i][j][q] = 0.0f;

    issue(0); cp_commit();
    issue(1); cp_commit();

    for (int kk = 0; kk < NKK; kk++) {
        cp_wait1();
        __syncthreads();
        if (kk + 2 < NKK) issue(kk + 2);
        cp_commit();

        const uint32_t st = sb + (kk % NSTAGE) * STAGE_BYTES;
        const uint32_t As = st, Ws = st + 16384;

#pragma unroll
        for (int ks = 0; ks < 4; ks++) {
            const int ch = ks * 2 + (lane >> 4);
            uint32_t a[4][4], w[2][4];
#pragma unroll
            for (int mt = 0; mt < 4; mt++) {
                int row = wm0 + mt * 16 + (lane & 15);
                uint32_t off = row * 128 + ((ch ^ (row & 7)) << 4);
                ldm_x4(a[mt], As + off);
            }
#pragma unroll
            for (int bt = 0; bt < 2; bt++) {
                int row = wn0 + bt * 16 + (lane & 15);
                uint32_t off = row * 128 + ((ch ^ (row & 7)) << 4);
                ldm_x4(w[bt], Ws + off);
            }
#pragma unroll
            for (int mt = 0; mt < 4; mt++)
#pragma unroll
                for (int nt = 0; nt < 4; nt++)
                    mma_f16(acc[mt][nt], a[mt], w[nt >> 1][nt & 1], w[nt >> 1][2 + (nt & 1)]);
        }
    }

    const bool is_tanh = (n0 < U_);
    const int grow = lane >> 2;
    const int gcol = (lane & 3) * 2;
#pragma unroll
    for (int mt = 0; mt < 4; mt++) {
#pragma unroll
        for (int nt = 0; nt < 4; nt++) {
            int n = n0 + wn0 + nt * 8 + gcol;
            float b0 = __ldg(bias + n);
            float b1 = __ldg(bias + n + 1);
#pragma unroll
            for (int h = 0; h < 2; h++) {
                int m = gm0 + wm0 + mt * 16 + grow + h * 8;
                float v0 = acc[mt][nt][2 * h]     + b0;
                float v1 = acc[mt][nt][2 * h + 1] + b1;
                if (is_tanh) {
                    float e0 = __expf(2.0f * v0), e1 = __expf(2.0f * v1);
                    v0 = 1.0f - 2.0f / (e0 + 1.0f);
                    v1 = 1.0f - 2.0f / (e1 + 1.0f);
                } else {
                    v0 = 1.0f / (1.0f + __expf(-v0));
                    v1 = 1.0f / (1.0f + __expf(-v1));
                }
                *(__half2*)(g_gates16 + (size_t)m * NG + n) = __floats2half2_rn(v0, v1);
            }
        }
    }
}

// ---------------------------------------------------------------------------
// Scan passes: fp16 gates, fp32 math. grid (1, S_, B_) = 512 blocks.
// scan_partial: NO unroll (measured best). scan_final: unroll 4, plain ld/st.
// ---------------------------------------------------------------------------
__global__ void __launch_bounds__(256) scan_partial() {
    int u = threadIdx.x * 2;
    int s = blockIdx.y;
    int b = blockIdx.z;
    const __half* gp = g_gates16 + ((size_t)(b * T_ + s * CH_)) * NG;
    float2 c = make_float2(0.f, 0.f), F = make_float2(1.f, 1.f);
    for (int t = 0; t < CH_; t++) {
        float2 x = __half22float2(*(const __half2*)(gp + (size_t)t * NG + u));
        float2 f = __half22float2(*(const __half2*)(gp + (size_t)t * NG + U_ + u));
        c.x = fmaf(f.x, c.x - x.x, x.x);
        c.y = fmaf(f.y, c.y - x.y, x.y);
        F.x *= f.x; F.y *= f.y;
    }
    int off = (b * S_ + s) * U_ + u;
    *(float2*)(g_cend  + off) = c;
    *(float2*)(g_fprod + off) = F;
}

__global__ void __launch_bounds__(256) scan_final(float* __restrict__ out) {
    int u = threadIdx.x * 2;
    int s = blockIdx.y;
    int b = blockIdx.z;

    float2 c = make_float2(0.f, 0.f);
#pragma unroll 4
    for (int sp = 0; sp < s; sp++) {
        int off = (b * S_ + sp) * U_ + u;
        float2 F = *(const float2*)(g_fprod + off);
        float2 E = *(const float2*)(g_cend  + off);
        c.x = fmaf(F.x, c.x, E.x);
        c.y = fmaf(F.y, c.y, E.y);
    }

    const __half* gp = g_gates16 + ((size_t)(b * T_ + s * CH_)) * NG;
    float* op = out + ((size_t)(b * T_ + s * CH_)) * U_;
#pragma unroll 4
    for (int t = 0; t < CH_; t++) {
        float2 x = __half22float2(*(const __half2*)(gp + (size_t)t * NG + u));
        float2 f = __half22float2(*(const __half2*)(gp + (size_t)t * NG + U_ + u));
        float2 o = __half22float2(*(const __half2*)(gp + (size_t)t * NG + 2 * U_ + u));
        c.x = fmaf(f.x, c.x - x.x, x.x);
        c.y = fmaf(f.y, c.y - x.y, x.y);
        *(float2*)(op + (size_t)t * U_ + u) = make_float2(o.x * c.x, o.y * c.y);
    }
}

// ---------------------------------------------------------------------------
extern "C" void kernel_launch(void* const* d_in, const int* in_sizes, int n_in,
                              void* d_out, int out_size) {
    const float* in   = (const float*)d_in[0];
    const float* W    = (const float*)d_in[1];
    const float* bias = (const float*)d_in[2];
    float* out = (float*)d_out;

    prep_fused<<<NWBLK + NABLK, 256>>>(in, W);

    cudaFuncSetAttribute(gemm_mma, cudaFuncAttributeMaxDynamicSharedMemorySize, SMEM_TOTAL);
    dim3 gGemm(NG / BN, (B_ * T_) / BM);   // (12, 256)
    gemm_mma<<<gGemm, 256, SMEM_TOTAL>>>(bias);

    dim3 gScan(1, S_, B_);                 // 512 blocks
    scan_partial<<<gScan, 256>>>();
    scan_final<<<gScan, 256>>>(out);
}